// round 9
// baseline (speedup 1.0000x reference)
#include <cuda_runtime.h>
#include <cuda_fp16.h>
#include <math.h>
#include <stdint.h>

// Problem constants (fixed by the dataset)
#define NB      8
#define LQ      300
#define CDIM    256
#define HEADS   8
#define NLVL    4
#define NPTS    8
#define DHEAD   32
#define LEN_IN  21760
#define NQ      (NB*LQ)         // 2400
#define MROWS   (NB*LEN_IN)     // 174080

// ---------------- scratch (device globals; no allocations allowed) ----------
__device__ __half   g_valh[(size_t)MROWS * CDIM];    // projected value (fp16), 89 MB
__device__ unsigned g_bits[NQ * 512];                // packed mask: word=(y*4+(x&3)), bit=x>>2
__device__ float    g_box[NQ * 4];                   // cx, cy, w, h
__device__ float    g_off[NQ * 512];                 // sampling offsets (h,l,p,2)
__device__ float    g_attn[NQ * 256];                // raw attention logits (h,l,p)
__device__ float    g_samp[NQ * 256];                // sampled output before W_out
// W_val^T fragments: ((ntile*8 + kpair)*32 + lane) -> uint4 {ks even b0,b1, ks odd b0,b1}
__device__ uint4    g_Bf4[32 * 8 * 32];
// [Woff | Wattn] (N=768) in B-fragment layout, fp16 hi/lo splits (3-term, exact).
__device__ uint2    g_PfHi[96 * 16 * 32];
__device__ uint2    g_PfLo[96 * 16 * 32];

// ---------------- helpers ----------------------------------------------------
__device__ __forceinline__ void mma16816(float* c, const uint32_t* a, const uint2 b) {
    asm volatile(
        "mma.sync.aligned.m16n8k16.row.col.f32.f16.f16.f32 "
        "{%0,%1,%2,%3}, {%4,%5,%6,%7}, {%8,%9}, {%0,%1,%2,%3};\n"
        : "+f"(c[0]), "+f"(c[1]), "+f"(c[2]), "+f"(c[3])
        : "r"(a[0]), "r"(a[1]), "r"(a[2]), "r"(a[3]), "r"(b.x), "r"(b.y));
}
__device__ __forceinline__ uint32_t cvt_h(float2 v) {
    __half2 h = __float22half2_rn(v);
    return *(uint32_t*)&h;
}
__device__ __forceinline__ void cvt_hilo(float2 v, uint32_t& hi, uint32_t& lo) {
    __half2 h = __float22half2_rn(v);
    float2 f = __half22float2(h);
    __half2 l = __float22half2_rn(make_float2(v.x - f.x, v.y - f.y));
    hi = *(uint32_t*)&h;
    lo = *(uint32_t*)&l;
}
__device__ __forceinline__ uint32_t smem_u32(const void* p) {
    uint32_t a;
    asm("{ .reg .u64 t; cvta.to.shared.u64 t, %1; cvt.u32.u64 %0, t; }" : "=r"(a) : "l"(p));
    return a;
}
__device__ __forceinline__ void ldm_x4(uint32_t* r, uint32_t addr) {
    asm volatile("ldmatrix.sync.aligned.m8n8.x4.shared.b16 {%0,%1,%2,%3}, [%4];"
        : "=r"(r[0]), "=r"(r[1]), "=r"(r[2]), "=r"(r[3]) : "r"(addr));
}

// ================= prep: W_val^T -> fp16 uint4 fragment pairs ===============
__global__ __launch_bounds__(256) void prep_Bval(const float* __restrict__ W) {
    int idx = blockIdx.x * 256 + threadIdx.x;     // 8192 threads
    int lane  = idx & 31;
    int gkp   = (idx >> 5) & 7;                   // k-pair 0..7
    int ntile = idx >> 8;                         // 0..31
    int n  = ntile * 8 + (lane >> 2);
    uint32_t r[4];
    #pragma unroll
    for (int h2 = 0; h2 < 2; h2++) {
        int kb = (gkp * 2 + h2) * 16 + (lane & 3) * 2;
        r[h2*2+0] = cvt_h(make_float2(W[(kb + 0) * 256 + n], W[(kb + 1) * 256 + n]));
        r[h2*2+1] = cvt_h(make_float2(W[(kb + 8) * 256 + n], W[(kb + 9) * 256 + n]));
    }
    g_Bf4[idx] = make_uint4(r[0], r[1], r[2], r[3]);
}

// ================= prep: [Woff | Wattn]^T -> fp16 hi/lo fragments ===========
__global__ __launch_bounds__(256) void prep_Bproj(
        const float* __restrict__ Woff, const float* __restrict__ Wattn) {
    int idx = blockIdx.x * 256 + threadIdx.x;     // 49152 threads
    int lane  = idx & 31;
    int ks    = (idx >> 5) & 15;
    int ntile = idx >> 9;                         // 0..95
    int n  = ntile * 8 + (lane >> 2);             // 0..767
    int kb = ks * 16 + (lane & 3) * 2;
    float x[4];
    #pragma unroll
    for (int q = 0; q < 4; q++) {
        int k = kb + (q >> 1) * 8 + (q & 1);
        x[q] = (n < 512) ? Woff[k * 512 + n] : Wattn[k * 256 + (n - 512)];
    }
    uint32_t h0, l0, h1, l1;
    cvt_hilo(make_float2(x[0], x[1]), h0, l0);
    cvt_hilo(make_float2(x[2], x[3]), h1, l1);
    g_PfHi[idx] = make_uint2(h0, h1);
    g_PfLo[idx] = make_uint2(l0, l1);
}

// ================= kernel: fp16 HMMA value GEMM (64x256 CTA tile) ===========
// 8 warps: 2(M)x4(N), warp tile 32x64. A: LDG float4 -> cvt fp16 in regs ->
// STS uint4 into a 2-stage ldmatrix tile (no fp32 smem staging at all).
// B fragment table (64 KB) stays L1-resident (only 18 KB smem carved out).
#define HROW    72                       // halves per fp16 row (144 B, conflict-free)
#define VSTAGE  (64 * HROW)              // halves per stage (9216 B)
#define VG_SMEM (2 * VSTAGE * 2)         // 18432 bytes

__global__ __launch_bounds__(256, 2) void value_gemm(
        const float* __restrict__ A, const unsigned char* __restrict__ pad,
        const float* __restrict__ bias) {
    extern __shared__ __half smh[];
    const uint32_t sbh = smem_u32(smh);
    const int tid = threadIdx.x, lane = tid & 31, wid = tid >> 5;
    const int g = lane >> 2, t = lane & 3;
    const int wm = (wid >> 2) * 32;          // warp M offset (0/32)
    const int wn = (wid & 3) * 64;           // warp N offset
    const int rowTile = blockIdx.x * 64;
    const int ntb = wn >> 3;

    float acc[2][8][4];
    #pragma unroll
    for (int i = 0; i < 2; i++)
        #pragma unroll
        for (int j = 0; j < 8; j++)
            #pragma unroll
            for (int q = 0; q < 4; q++) acc[i][j][q] = 0.f;

    // load/convert/store mapping: thread (crow, ccg) owns 16 cols of one row
    const int crow = tid >> 2, ccg = tid & 3;
    const float* aptr = A + (size_t)(rowTile + crow) * 256 + ccg * 16;

    float4 raw[4];
    uint32_t hb[8];
    #define LDG_A(c) { \
        raw[0] = *(const float4*)(aptr + (c) * 64 + 0); \
        raw[1] = *(const float4*)(aptr + (c) * 64 + 4); \
        raw[2] = *(const float4*)(aptr + (c) * 64 + 8); \
        raw[3] = *(const float4*)(aptr + (c) * 64 + 12); }
    #define CVT_A() { \
        _Pragma("unroll") \
        for (int q = 0; q < 4; q++) { \
            hb[2*q+0] = cvt_h(make_float2(raw[q].x, raw[q].y)); \
            hb[2*q+1] = cvt_h(make_float2(raw[q].z, raw[q].w)); \
        } }
    #define STS_A(s) { \
        uint4* dst = (uint4*)(smh + (s) * VSTAGE + crow * HROW + ccg * 16); \
        dst[0] = make_uint4(hb[0], hb[1], hb[2], hb[3]); \
        dst[1] = make_uint4(hb[4], hb[5], hb[6], hb[7]); }

    LDG_A(0); CVT_A(); STS_A(0);
    __syncthreads();

    #pragma unroll
    for (int c = 0; c < 4; c++) {
        const int st = c & 1;
        if (c < 3) LDG_A(c + 1);          // prefetch; MMA phase hides latency

        const uint32_t stb = sbh + st * (VSTAGE * 2);
        #pragma unroll
        for (int kp = 0; kp < 2; kp++) {
            // B for this k-pair in two j-groups of 4 (bounds reg pressure)
            uint4 b4[4];
            #pragma unroll
            for (int jj = 0; jj < 4; jj++)
                b4[jj] = g_Bf4[((ntb + jj) * 8 + c * 2 + kp) * 32 + lane];
            uint32_t a[2][2][4];          // [h2][i]
            #pragma unroll
            for (int h2 = 0; h2 < 2; h2++) {
                const int ksl = kp * 2 + h2;
                #pragma unroll
                for (int i = 0; i < 2; i++) {
                    int lrow = wm + i * 16 + (lane & 15);
                    ldm_x4(a[h2][i], stb + lrow * (HROW * 2) + ksl * 32 + ((lane >> 4) << 4));
                }
            }
            #pragma unroll
            for (int h2 = 0; h2 < 2; h2++)
                #pragma unroll
                for (int i = 0; i < 2; i++)
                    #pragma unroll
                    for (int jj = 0; jj < 4; jj++)
                        mma16816(acc[i][jj], a[h2][i],
                                 h2 ? make_uint2(b4[jj].z, b4[jj].w)
                                    : make_uint2(b4[jj].x, b4[jj].y));
            #pragma unroll
            for (int jj = 0; jj < 4; jj++)
                b4[jj] = g_Bf4[((ntb + 4 + jj) * 8 + c * 2 + kp) * 32 + lane];
            #pragma unroll
            for (int h2 = 0; h2 < 2; h2++)
                #pragma unroll
                for (int i = 0; i < 2; i++)
                    #pragma unroll
                    for (int jj = 0; jj < 4; jj++)
                        mma16816(acc[i][4 + jj], a[h2][i],
                                 h2 ? make_uint2(b4[jj].z, b4[jj].w)
                                    : make_uint2(b4[jj].x, b4[jj].y));
        }
        if (c < 3) {
            CVT_A(); STS_A(st ^ 1);       // other stage; prior readers done (sync below)
            __syncthreads();              // publish before next MMA phase
        }
    }
    #undef LDG_A
    #undef CVT_A
    #undef STS_A

    // ---- epilogue: bias add, padding zero, fp16 stores
    #pragma unroll
    for (int i = 0; i < 2; i++) {
        int ra = rowTile + wm + i * 16 + g;
        int rb = ra + 8;
        bool pa = pad[ra] != 0, pb = pad[rb] != 0;
        #pragma unroll
        for (int j = 0; j < 8; j++) {
            int c0 = wn + j * 8 + t * 2;
            float2 bi = *(const float2*)(bias + c0);
            float2 oa, ob;
            oa.x = pa ? 0.f : acc[i][j][0] + bi.x;
            oa.y = pa ? 0.f : acc[i][j][1] + bi.y;
            ob.x = pb ? 0.f : acc[i][j][2] + bi.x;
            ob.y = pb ? 0.f : acc[i][j][3] + bi.y;
            *(__half2*)(g_valh + (size_t)ra * 256 + c0) = __float22half2_rn(oa);
            *(__half2*)(g_valh + (size_t)rb * 256 + c0) = __float22half2_rn(ob);
        }
    }
}

// ================= kernel: HMMA 3-term fp16 proj GEMM =======================
__global__ __launch_bounds__(256) void proj_gemm(
        const float* __restrict__ Q,
        const float* __restrict__ boff, const float* __restrict__ battn) {
    const int tid = threadIdx.x, lane = tid & 31, wid = tid >> 5;
    const int g = lane >> 2, t = lane & 3;
    const int rowBase = blockIdx.x * 128 + (wid & 3) * 32 + g;
    const int colBase = blockIdx.y * 128 + (wid >> 2) * 64;
    const int ntb = colBase >> 3;

    float2 bias2[8];
    #pragma unroll
    for (int j = 0; j < 8; j++) {
        int c = colBase + j * 8 + t * 2;
        bias2[j] = (c < 512) ? *(const float2*)(boff + c)
                             : *(const float2*)(battn + (c - 512));
    }

    float acc[2][8][4];
    #pragma unroll
    for (int i = 0; i < 2; i++)
        #pragma unroll
        for (int j = 0; j < 8; j++)
            #pragma unroll
            for (int q = 0; q < 4; q++) acc[i][j][q] = 0.f;

    float2 araw[2][2][4];
    #define LOAD_AQ(ks, buf) { \
        _Pragma("unroll") \
        for (int i = 0; i < 2; i++) { \
            int r0 = min(rowBase + i * 16, NQ - 1); \
            int r1 = min(rowBase + i * 16 + 8, NQ - 1); \
            const float* b0 = Q + (size_t)r0 * 256 + (ks) * 16 + t * 2; \
            const float* b1 = Q + (size_t)r1 * 256 + (ks) * 16 + t * 2; \
            araw[buf][i][0] = *(const float2*)(b0); \
            araw[buf][i][1] = *(const float2*)(b1); \
            araw[buf][i][2] = *(const float2*)(b0 + 8); \
            araw[buf][i][3] = *(const float2*)(b1 + 8); \
        } }

    LOAD_AQ(0, 0);
    #pragma unroll
    for (int ks = 0; ks < 16; ks++) {
        const int cur = ks & 1;
        if (ks < 15) LOAD_AQ(ks + 1, cur ^ 1);

        uint2 bhi[8], blo[8];
        #pragma unroll
        for (int j = 0; j < 8; j++) {
            int bidx = ((ntb + j) * 16 + ks) * 32 + lane;
            bhi[j] = g_PfHi[bidx];
            blo[j] = g_PfLo[bidx];
        }
        uint32_t ahi[2][4], alo[2][4];
        #pragma unroll
        for (int i = 0; i < 2; i++)
            #pragma unroll
            for (int q = 0; q < 4; q++)
                cvt_hilo(araw[cur][i][q], ahi[i][q], alo[i][q]);

        #pragma unroll
        for (int i = 0; i < 2; i++)
            #pragma unroll
            for (int j = 0; j < 8; j++) {
                mma16816(acc[i][j], ahi[i], bhi[j]);
                mma16816(acc[i][j], ahi[i], blo[j]);
                mma16816(acc[i][j], alo[i], bhi[j]);
            }
    }
    #undef LOAD_AQ

    #pragma unroll
    for (int i = 0; i < 2; i++) {
        #pragma unroll
        for (int q2 = 0; q2 < 2; q2++) {
            int r = rowBase + i * 16 + q2 * 8;
            if (r >= NQ) continue;
            #pragma unroll
            for (int j = 0; j < 8; j++) {
                int c0 = colBase + j * 8 + t * 2;
                float2 o;
                o.x = acc[i][j][q2 * 2 + 0] + bias2[j].x;
                o.y = acc[i][j][q2 * 2 + 1] + bias2[j].y;
                if (c0 < 512) *(float2*)(g_off  + (size_t)r * 512 + c0)         = o;
                else          *(float2*)(g_attn + (size_t)r * 256 + (c0 - 512)) = o;
            }
        }
    }
}

// ---------------- kernel 1: mask -> packed bits + bounding box ---------------
__global__ __launch_bounds__(256) void mask_kernel(const float* __restrict__ masks) {
    int b = blockIdx.x;
    const float4* m = (const float4*)(masks + (size_t)b * 16384);
    __shared__ unsigned colOrW[8][4];
    __shared__ unsigned char rowAny[128];
    __shared__ unsigned rowBits[4];
    int t = threadIdx.x, lane = t & 31, w = t >> 5;
    unsigned co[4] = {0, 0, 0, 0};
    unsigned* bo = g_bits + (size_t)b * 512;

    #pragma unroll
    for (int it = 0; it < 16; it++) {
        int row = it * 8 + w;
        float4 v = m[row * 32 + lane];
        unsigned b0 = __ballot_sync(0xffffffffu, v.x > 0.f);
        unsigned b1 = __ballot_sync(0xffffffffu, v.y > 0.f);
        unsigned b2 = __ballot_sync(0xffffffffu, v.z > 0.f);
        unsigned b3 = __ballot_sync(0xffffffffu, v.w > 0.f);
        co[0] |= b0; co[1] |= b1; co[2] |= b2; co[3] |= b3;
        if (lane == 0) rowAny[row] = ((b0 | b1 | b2 | b3) != 0u);
        if (lane < 4) {
            unsigned bb = (lane == 0) ? b0 : (lane == 1) ? b1 : (lane == 2) ? b2 : b3;
            bo[row * 4 + lane] = bb;
        }
    }
    if (lane < 4)
        colOrW[w][lane] = (lane == 0) ? co[0] : (lane == 1) ? co[1] : (lane == 2) ? co[2] : co[3];
    __syncthreads();

    if (t < 128) {
        unsigned rb = __ballot_sync(0xffffffffu, rowAny[t] != 0);
        if (lane == 0) rowBits[t >> 5] = rb;
    }
    __syncthreads();

    if (t == 0) {
        int xmin = 128, xmax = -1, ymin = 128, ymax = -1;
        #pragma unroll
        for (int j = 0; j < 4; j++) {
            unsigned v = 0;
            #pragma unroll
            for (int ww = 0; ww < 8; ww++) v |= colOrW[ww][j];
            if (v) {
                int lo = 4 * (__ffs(v) - 1) + j;  if (lo < xmin) xmin = lo;
                int hi = 4 * (31 - __clz(v)) + j; if (hi > xmax) xmax = hi;
            }
            unsigned r = rowBits[j];
            if (r) {
                int lo = __ffs(r) - 1 + 32 * j;  if (lo < ymin) ymin = lo;
                int hi = 31 - __clz(r) + 32 * j; if (hi > ymax) ymax = hi;
            }
        }
        float4 box;
        if (xmax >= 0) {
            float x0 = xmin * (1.f/128.f), x1 = (xmax + 1) * (1.f/128.f);
            float y0 = ymin * (1.f/128.f), y1 = (ymax + 1) * (1.f/128.f);
            box = make_float4((x0 + x1) * 0.5f, (y0 + y1) * 0.5f, x1 - x0, y1 - y0);
        } else {
            box = make_float4(0.f, 0.f, 0.f, 0.f);
        }
        ((float4*)g_box)[b] = box;
    }
}

// ---------------- fp32 tiled SGEMM (small out-projection only) --------------
template<int BM, int BN, int BK, int TM, int TN>
__global__ __launch_bounds__((BM/TM)*(BN/TN))
void sgemm_kernel(const float* __restrict__ A, const float* __restrict__ B,
                  const float* __restrict__ bias,
                  float* __restrict__ Cmat, int M, int N, int K) {
    constexpr int THREADS = (BM/TM)*(BN/TN);
    __shared__ float As[BK][BM];
    __shared__ float Bs[BK][BN];
    const int block_row = blockIdx.y * BM;
    const int block_col = blockIdx.x * BN;
    const int tid  = threadIdx.x;
    const int tcol = tid % (BN/TN);
    const int trow = tid / (BN/TN);

    float acc[TM][TN];
    #pragma unroll
    for (int i = 0; i < TM; i++)
        #pragma unroll
        for (int j = 0; j < TN; j++) acc[i][j] = 0.f;

    constexpr int AV = (BM*BK)/(4*THREADS);
    constexpr int BV = (BK*BN)/(4*THREADS);

    for (int k0 = 0; k0 < K; k0 += BK) {
        #pragma unroll
        for (int i = 0; i < AV; i++) {
            int v = tid + i * THREADS;
            int r  = v / (BK/4);
            int c4 = (v % (BK/4)) * 4;
            int rg = block_row + r; if (rg > M - 1) rg = M - 1;
            float4 a = *(const float4*)(A + (size_t)rg * K + k0 + c4);
            As[c4+0][r] = a.x; As[c4+1][r] = a.y; As[c4+2][r] = a.z; As[c4+3][r] = a.w;
        }
        #pragma unroll
        for (int i = 0; i < BV; i++) {
            int v = tid + i * THREADS;
            int r  = v / (BN/4);
            int c4 = (v % (BN/4)) * 4;
            *(float4*)(&Bs[r][c4]) = *(const float4*)(B + (size_t)(k0 + r) * N + block_col + c4);
        }
        __syncthreads();

        #pragma unroll
        for (int k = 0; k < BK; k++) {
            float ra[TM], rb[TN];
            #pragma unroll
            for (int i = 0; i < TM/2; i++) {
                ra[i]        = As[k][trow*(TM/2) + i];
                ra[i + TM/2] = As[k][BM/2 + trow*(TM/2) + i];
            }
            #pragma unroll
            for (int j = 0; j < TN/2; j++) {
                rb[j]        = Bs[k][tcol*(TN/2) + j];
                rb[j + TN/2] = Bs[k][BN/2 + tcol*(TN/2) + j];
            }
            #pragma unroll
            for (int i = 0; i < TM; i++)
                #pragma unroll
                for (int j = 0; j < TN; j++)
                    acc[i][j] += ra[i] * rb[j];
        }
        __syncthreads();
    }

    #pragma unroll
    for (int i = 0; i < TM; i++) {
        int rr = (i < TM/2) ? trow*(TM/2) + i : BM/2 + trow*(TM/2) + (i - TM/2);
        int r = block_row + rr;
        if (r >= M) continue;
        #pragma unroll
        for (int j = 0; j < TN; j++) {
            int cc = (j < TN/2) ? tcol*(TN/2) + j : BN/2 + tcol*(TN/2) + (j - TN/2);
            int c = block_col + cc;
            Cmat[(size_t)r * N + c] = acc[i][j] + bias[c];
        }
    }
}

// ---------------- kernel 4: sampling + softmax + bilinear gather -------------
__global__ __launch_bounds__(256) void sample_kernel() {
    int b = blockIdx.x;
    int n = b / LQ;
    int t = threadIdx.x, lane = t & 31, h = t >> 5;
    __shared__ int   s_idx[8][32][4];
    __shared__ float s_w[8][32][4];

    const int Wl_[4]    = {128, 64, 32, 16};
    const int start_[4] = {0, 16384, 20480, 21504};

    float4 box = ((const float4*)g_box)[b];

    int p = lane, l = p >> 3;
    float ox = g_off[(size_t)b * 512 + (h * 32 + p) * 2 + 0];
    float oy = g_off[(size_t)b * 512 + (h * 32 + p) * 2 + 1];
    float locx = box.x + ox * (1.f / 16.f) * box.z;
    float locy = box.y + oy * (1.f / 16.f) * box.w;

    int px = (int)(locx * 128.f); px = min(max(px, 0), 127);
    int py = (int)(locy * 128.f); py = min(max(py, 0), 127);
    // layout: word = y*4 + (x&3), bit = x>>2
    unsigned wbits = g_bits[(size_t)b * 512 + py * 4 + (px & 3)];
    float pin = ((wbits >> (px >> 2)) & 1u) ? 1.f : 0.f;

    float logit = g_attn[(size_t)b * 256 + h * 32 + p] * pin;
    float mx = logit;
    #pragma unroll
    for (int o = 16; o; o >>= 1) mx = fmaxf(mx, __shfl_xor_sync(0xffffffffu, mx, o));
    float e = expf(logit - mx);
    float sm = e;
    #pragma unroll
    for (int o = 16; o; o >>= 1) sm += __shfl_xor_sync(0xffffffffu, sm, o);
    float aw = e / sm;

    int Wl = Wl_[l], Hl = Wl;
    float pxf = locx * (float)Wl - 0.5f;
    float pyf = locy * (float)Hl - 0.5f;
    float x0f = floorf(pxf), y0f = floorf(pyf);
    float wx = pxf - x0f, wy = pyf - y0f;
    int x0 = (int)x0f, y0 = (int)y0f;
    int base = n * LEN_IN + start_[l];

    #pragma unroll
    for (int k = 0; k < 4; k++) {
        int xi = x0 + (k & 1), yi = y0 + (k >> 1);
        float cw = ((k & 1) ? wx : 1.f - wx) * ((k >> 1) ? wy : 1.f - wy);
        bool valid = (xi >= 0) && (xi < Wl) && (yi >= 0) && (yi < Hl);
        int xc = min(max(xi, 0), Wl - 1);
        int yc = min(max(yi, 0), Hl - 1);
        s_idx[h][p][k] = base + yc * Wl + xc;
        s_w[h][p][k]   = valid ? cw * aw : 0.f;
    }
    __syncwarp();

    int d = lane;
    const __half* vcol = g_valh + h * 32 + d;
    float acc = 0.f;
    #pragma unroll 4
    for (int pp = 0; pp < 32; pp++) {
        #pragma unroll
        for (int k = 0; k < 4; k++) {
            float wgt = s_w[h][pp][k];
            if (wgt != 0.f)
                acc += wgt * __half2float(vcol[(size_t)s_idx[h][pp][k] * 256]);
        }
    }
    g_samp[(size_t)b * 256 + h * 32 + d] = acc;
}

// ---------------- launch --------------------------------------------------
extern "C" void kernel_launch(void* const* d_in, const int* in_sizes, int n_in,
                              void* d_out, int out_size) {
    const float* query = (const float*)d_in[0];
    const float* masks = (const float*)d_in[2];
    const float* flat  = (const float*)d_in[4];
    const unsigned char* pad = (const unsigned char*)d_in[7];
    const float* Woff  = (const float*)d_in[8];
    const float* boff  = (const float*)d_in[9];
    const float* Wattn = (const float*)d_in[10];
    const float* battn = (const float*)d_in[11];
    const float* Wval  = (const float*)d_in[12];
    const float* bval  = (const float*)d_in[13];
    const float* Wout  = (const float*)d_in[14];
    const float* bout  = (const float*)d_in[15];
    float* out = (float*)d_out;

    float* sampp = nullptr;
    cudaGetSymbolAddress((void**)&sampp, g_samp);

    cudaFuncSetAttribute(value_gemm, cudaFuncAttributeMaxDynamicSharedMemorySize, VG_SMEM);

    // --- fork two side streams off the capture stream (capture-safe pattern)
    cudaStream_t s1, s2;
    cudaStreamCreateWithFlags(&s1, cudaStreamNonBlocking);
    cudaStreamCreateWithFlags(&s2, cudaStreamNonBlocking);
    cudaEvent_t evRoot, ev1, ev2;
    cudaEventCreateWithFlags(&evRoot, cudaEventDisableTiming);
    cudaEventCreateWithFlags(&ev1, cudaEventDisableTiming);
    cudaEventCreateWithFlags(&ev2, cudaEventDisableTiming);

    cudaEventRecord(evRoot, 0);
    cudaStreamWaitEvent(s1, evRoot, 0);
    cudaStreamWaitEvent(s2, evRoot, 0);

    // main stream: value-projection path (tensor/L1-bound)
    prep_Bval<<<32, 256>>>(Wval);
    value_gemm<<<MROWS/64, 256, VG_SMEM>>>(flat, pad, bval);

    // s1: mask path (DRAM-bound) — overlaps value_gemm
    mask_kernel<<<NQ, 256, 0, s1>>>(masks);

    // s2: offsets/logits projection — overlaps value_gemm
    prep_Bproj<<<192, 256, 0, s2>>>(Woff, Wattn);
    proj_gemm<<<dim3((NQ + 127)/128, 6), 256, 0, s2>>>(query, boff, battn);

    // join
    cudaEventRecord(ev1, s1);
    cudaEventRecord(ev2, s2);
    cudaStreamWaitEvent(0, ev1, 0);
    cudaStreamWaitEvent(0, ev2, 0);

    // softmax + bilinear sampling, then out-projection
    sample_kernel<<<NQ, 256>>>();
    sgemm_kernel<64,64,16,4,4><<<dim3(CDIM/64, (NQ + 63)/64), 256>>>(
        sampp, Wout, bout, out, NQ, CDIM, CDIM);

    // destroy only when NOT capturing (destroying capture-attached objects
    // would invalidate the graph); leaked once on the capture call is fine.
    cudaStreamCaptureStatus st = cudaStreamCaptureStatusNone;
    cudaStreamIsCapturing(0, &st);
    if (st == cudaStreamCaptureStatusNone) {
        cudaEventDestroy(evRoot);
        cudaEventDestroy(ev1);
        cudaEventDestroy(ev2);
        cudaStreamDestroy(s1);
        cudaStreamDestroy(s2);
    }
}

// round 11
// speedup vs baseline: 1.0462x; 1.0462x over previous
#include <cuda_runtime.h>
#include <cuda_fp16.h>
#include <math.h>
#include <stdint.h>

// Problem constants (fixed by the dataset)
#define NB      8
#define LQ      300
#define CDIM    256
#define HEADS   8
#define NLVL    4
#define NPTS    8
#define DHEAD   32
#define LEN_IN  21760
#define NQ      (NB*LQ)         // 2400
#define MROWS   (NB*LEN_IN)     // 174080

// ---------------- scratch (device globals; no allocations allowed) ----------
__device__ __half   g_valh[(size_t)MROWS * CDIM];    // projected value (fp16), 89 MB
__device__ unsigned g_bits[NQ * 512];                // packed mask: word=(y*4+(x&3)), bit=x>>2
__device__ float    g_box[NQ * 4];                   // cx, cy, w, h
__device__ float    g_off[NQ * 512];                 // sampling offsets (h,l,p,2)
__device__ float    g_attn[NQ * 256];                // raw attention logits (h,l,p)
__device__ float    g_samp[NQ * 256];                // sampled output before W_out
// W_val^T fragments: ((ntile*8 + kpair)*32 + lane) -> uint4 {ks even b0,b1, ks odd b0,b1}
__device__ uint4    g_Bf4[32 * 8 * 32];
// [Woff | Wattn] (N=768) in B-fragment layout, fp16 hi/lo splits (3-term, exact).
__device__ uint2    g_PfHi[96 * 16 * 32];
__device__ uint2    g_PfLo[96 * 16 * 32];

// ---------------- helpers ----------------------------------------------------
__device__ __forceinline__ void mma16816(float* c, const uint32_t* a, const uint2 b) {
    asm volatile(
        "mma.sync.aligned.m16n8k16.row.col.f32.f16.f16.f32 "
        "{%0,%1,%2,%3}, {%4,%5,%6,%7}, {%8,%9}, {%0,%1,%2,%3};\n"
        : "+f"(c[0]), "+f"(c[1]), "+f"(c[2]), "+f"(c[3])
        : "r"(a[0]), "r"(a[1]), "r"(a[2]), "r"(a[3]), "r"(b.x), "r"(b.y));
}
__device__ __forceinline__ uint32_t cvt_h(float2 v) {
    __half2 h = __float22half2_rn(v);
    return *(uint32_t*)&h;
}
__device__ __forceinline__ void cvt_hilo(float2 v, uint32_t& hi, uint32_t& lo) {
    __half2 h = __float22half2_rn(v);
    float2 f = __half22float2(h);
    __half2 l = __float22half2_rn(make_float2(v.x - f.x, v.y - f.y));
    hi = *(uint32_t*)&h;
    lo = *(uint32_t*)&l;
}
__device__ __forceinline__ uint32_t smem_u32(const void* p) {
    uint32_t a;
    asm("{ .reg .u64 t; cvta.to.shared.u64 t, %1; cvt.u32.u64 %0, t; }" : "=r"(a) : "l"(p));
    return a;
}
__device__ __forceinline__ void cp_async16(uint32_t dst, const void* src) {
    asm volatile("cp.async.cg.shared.global [%0], [%1], 16;" :: "r"(dst), "l"(src));
}
__device__ __forceinline__ void cp_commit() { asm volatile("cp.async.commit_group;" ::: "memory"); }
template<int N> __device__ __forceinline__ void cp_wait() {
    asm volatile("cp.async.wait_group %0;" :: "n"(N) : "memory");
}
__device__ __forceinline__ void ldm_x4(uint32_t* r, uint32_t addr) {
    asm volatile("ldmatrix.sync.aligned.m8n8.x4.shared.b16 {%0,%1,%2,%3}, [%4];"
        : "=r"(r[0]), "=r"(r[1]), "=r"(r[2]), "=r"(r[3]) : "r"(addr));
}

// ================= prep: W_val^T -> fp16 uint4 fragment pairs ===============
__global__ __launch_bounds__(256) void prep_Bval(const float* __restrict__ W) {
    int idx = blockIdx.x * 256 + threadIdx.x;     // 8192 threads
    int lane  = idx & 31;
    int gkp   = (idx >> 5) & 7;                   // k-pair 0..7
    int ntile = idx >> 8;                         // 0..31
    int n  = ntile * 8 + (lane >> 2);
    uint32_t r[4];
    #pragma unroll
    for (int h2 = 0; h2 < 2; h2++) {
        int kb = (gkp * 2 + h2) * 16 + (lane & 3) * 2;
        r[h2*2+0] = cvt_h(make_float2(W[(kb + 0) * 256 + n], W[(kb + 1) * 256 + n]));
        r[h2*2+1] = cvt_h(make_float2(W[(kb + 8) * 256 + n], W[(kb + 9) * 256 + n]));
    }
    g_Bf4[idx] = make_uint4(r[0], r[1], r[2], r[3]);
}

// ================= prep: [Woff | Wattn]^T -> fp16 hi/lo fragments ===========
__global__ __launch_bounds__(256) void prep_Bproj(
        const float* __restrict__ Woff, const float* __restrict__ Wattn) {
    int idx = blockIdx.x * 256 + threadIdx.x;     // 49152 threads
    int lane  = idx & 31;
    int ks    = (idx >> 5) & 15;
    int ntile = idx >> 9;                         // 0..95
    int n  = ntile * 8 + (lane >> 2);             // 0..767
    int kb = ks * 16 + (lane & 3) * 2;
    float x[4];
    #pragma unroll
    for (int q = 0; q < 4; q++) {
        int k = kb + (q >> 1) * 8 + (q & 1);
        x[q] = (n < 512) ? Woff[k * 512 + n] : Wattn[k * 256 + (n - 512)];
    }
    uint32_t h0, l0, h1, l1;
    cvt_hilo(make_float2(x[0], x[1]), h0, l0);
    cvt_hilo(make_float2(x[2], x[3]), h1, l1);
    g_PfHi[idx] = make_uint2(h0, h1);
    g_PfLo[idx] = make_uint2(l0, l1);
}

// ================= kernel: fp16 HMMA value GEMM (64x256 CTA tile) ===========
// 8 warps: 2(M)x4(N), warp tile 32x64. fp32 A staged via 3-deep cp.async,
// cooperatively converted to an fp16 smem tile, consumed via ldmatrix.x4.
// (R6/R8 configuration — measured 107.6us.)
#define SROWF   68                       // floats per fp32 stage row (64 + 4 pad)
#define STAGEF  (64 * SROWF)             // floats per stage
#define HROW    72                       // halves per fp16 row (144 B, conflict-free)
#define HBUF_B  (64 * HROW * 2)          // 9216 bytes
#define VG_SMEM (3 * STAGEF * 4 + HBUF_B)  // 61440 bytes

__global__ __launch_bounds__(256, 2) void value_gemm(
        const float* __restrict__ A, const unsigned char* __restrict__ pad,
        const float* __restrict__ bias) {
    extern __shared__ float smf[];
    __half* smh = (__half*)(smf + 3 * STAGEF);
    const uint32_t sb  = smem_u32(smf);
    const uint32_t sbh = smem_u32(smh);
    const int tid = threadIdx.x, lane = tid & 31, wid = tid >> 5;
    const int g = lane >> 2, t = lane & 3;
    const int wm = (wid >> 2) * 32;          // warp M offset (0/32)
    const int wn = (wid & 3) * 64;           // warp N offset
    const int rowTile = blockIdx.x * 64;
    const int ntb = wn >> 3;

    float acc[2][8][4];
    #pragma unroll
    for (int i = 0; i < 2; i++)
        #pragma unroll
        for (int j = 0; j < 8; j++)
            #pragma unroll
            for (int q = 0; q < 4; q++) acc[i][j][q] = 0.f;

    #define ISSUE_A(c, s) { \
        _Pragma("unroll") \
        for (int u4 = 0; u4 < 4; u4++) { \
            int u = tid + u4 * 256; \
            int row = u >> 4, seg = u & 15; \
            cp_async16(sb + ((s) * STAGEF + row * SROWF + seg * 4) * 4, \
                       A + (size_t)(rowTile + row) * 256 + (c) * 64 + seg * 4); \
        } \
        cp_commit(); }

    ISSUE_A(0, 0);
    ISSUE_A(1, 1);

    const int crow = tid >> 2, ccg = tid & 3;        // convert-phase mapping

    #pragma unroll
    for (int c = 0; c < 4; c++) {
        if (c < 3) cp_wait<1>(); else cp_wait<0>();
        __syncthreads();                              // stage ready + hbuf free

        // ---- cooperative fp32 -> fp16 conversion into ldmatrix-layout tile
        {
            const float* src = smf + (c % 3) * STAGEF + crow * SROWF + ccg * 16;
            uint32_t h[8];
            #pragma unroll
            for (int i = 0; i < 8; i++)
                h[i] = cvt_h(make_float2(src[2*i], src[2*i+1]));
            uint4* dst = (uint4*)(smh + crow * HROW + ccg * 16);
            dst[0] = make_uint4(h[0], h[1], h[2], h[3]);
            dst[1] = make_uint4(h[4], h[5], h[6], h[7]);
        }
        __syncthreads();
        if (c < 2) ISSUE_A(c + 2, (c + 2) % 3);

        // ---- MMA phase: A via ldmatrix, B via uint4 LDG (2 k-steps/load)
        #pragma unroll
        for (int kp = 0; kp < 2; kp++) {
            uint4 b4[8];
            #pragma unroll
            for (int j = 0; j < 8; j++)
                b4[j] = g_Bf4[((ntb + j) * 8 + c * 2 + kp) * 32 + lane];
            #pragma unroll
            for (int h2 = 0; h2 < 2; h2++) {
                const int ksl = kp * 2 + h2;
                uint32_t a[2][4];
                #pragma unroll
                for (int i = 0; i < 2; i++) {
                    int lrow = wm + i * 16 + (lane & 15);
                    ldm_x4(a[i], sbh + lrow * (HROW * 2) + ksl * 32 + ((lane >> 4) << 4));
                }
                #pragma unroll
                for (int i = 0; i < 2; i++)
                    #pragma unroll
                    for (int j = 0; j < 8; j++)
                        mma16816(acc[i][j], a[i],
                                 h2 ? make_uint2(b4[j].z, b4[j].w)
                                    : make_uint2(b4[j].x, b4[j].y));
            }
        }
    }
    #undef ISSUE_A

    // ---- epilogue: bias add, padding zero, fp16 stores
    #pragma unroll
    for (int i = 0; i < 2; i++) {
        int ra = rowTile + wm + i * 16 + g;
        int rb = ra + 8;
        bool pa = pad[ra] != 0, pb = pad[rb] != 0;
        #pragma unroll
        for (int j = 0; j < 8; j++) {
            int c0 = wn + j * 8 + t * 2;
            float2 bi = *(const float2*)(bias + c0);
            float2 oa, ob;
            oa.x = pa ? 0.f : acc[i][j][0] + bi.x;
            oa.y = pa ? 0.f : acc[i][j][1] + bi.y;
            ob.x = pb ? 0.f : acc[i][j][2] + bi.x;
            ob.y = pb ? 0.f : acc[i][j][3] + bi.y;
            *(__half2*)(g_valh + (size_t)ra * 256 + c0) = __float22half2_rn(oa);
            *(__half2*)(g_valh + (size_t)rb * 256 + c0) = __float22half2_rn(ob);
        }
    }
}

// ================= kernel: HMMA 3-term fp16 proj GEMM =======================
__global__ __launch_bounds__(256) void proj_gemm(
        const float* __restrict__ Q,
        const float* __restrict__ boff, const float* __restrict__ battn) {
    const int tid = threadIdx.x, lane = tid & 31, wid = tid >> 5;
    const int g = lane >> 2, t = lane & 3;
    const int rowBase = blockIdx.x * 128 + (wid & 3) * 32 + g;
    const int colBase = blockIdx.y * 128 + (wid >> 2) * 64;
    const int ntb = colBase >> 3;

    float2 bias2[8];
    #pragma unroll
    for (int j = 0; j < 8; j++) {
        int c = colBase + j * 8 + t * 2;
        bias2[j] = (c < 512) ? *(const float2*)(boff + c)
                             : *(const float2*)(battn + (c - 512));
    }

    float acc[2][8][4];
    #pragma unroll
    for (int i = 0; i < 2; i++)
        #pragma unroll
        for (int j = 0; j < 8; j++)
            #pragma unroll
            for (int q = 0; q < 4; q++) acc[i][j][q] = 0.f;

    float2 araw[2][2][4];
    #define LOAD_AQ(ks, buf) { \
        _Pragma("unroll") \
        for (int i = 0; i < 2; i++) { \
            int r0 = min(rowBase + i * 16, NQ - 1); \
            int r1 = min(rowBase + i * 16 + 8, NQ - 1); \
            const float* b0 = Q + (size_t)r0 * 256 + (ks) * 16 + t * 2; \
            const float* b1 = Q + (size_t)r1 * 256 + (ks) * 16 + t * 2; \
            araw[buf][i][0] = *(const float2*)(b0); \
            araw[buf][i][1] = *(const float2*)(b1); \
            araw[buf][i][2] = *(const float2*)(b0 + 8); \
            araw[buf][i][3] = *(const float2*)(b1 + 8); \
        } }

    LOAD_AQ(0, 0);
    #pragma unroll
    for (int ks = 0; ks < 16; ks++) {
        const int cur = ks & 1;
        if (ks < 15) LOAD_AQ(ks + 1, cur ^ 1);

        uint2 bhi[8], blo[8];
        #pragma unroll
        for (int j = 0; j < 8; j++) {
            int bidx = ((ntb + j) * 16 + ks) * 32 + lane;
            bhi[j] = g_PfHi[bidx];
            blo[j] = g_PfLo[bidx];
        }
        uint32_t ahi[2][4], alo[2][4];
        #pragma unroll
        for (int i = 0; i < 2; i++)
            #pragma unroll
            for (int q = 0; q < 4; q++)
                cvt_hilo(araw[cur][i][q], ahi[i][q], alo[i][q]);

        #pragma unroll
        for (int i = 0; i < 2; i++)
            #pragma unroll
            for (int j = 0; j < 8; j++) {
                mma16816(acc[i][j], ahi[i], bhi[j]);
                mma16816(acc[i][j], ahi[i], blo[j]);
                mma16816(acc[i][j], alo[i], bhi[j]);
            }
    }
    #undef LOAD_AQ

    #pragma unroll
    for (int i = 0; i < 2; i++) {
        #pragma unroll
        for (int q2 = 0; q2 < 2; q2++) {
            int r = rowBase + i * 16 + q2 * 8;
            if (r >= NQ) continue;
            #pragma unroll
            for (int j = 0; j < 8; j++) {
                int c0 = colBase + j * 8 + t * 2;
                float2 o;
                o.x = acc[i][j][q2 * 2 + 0] + bias2[j].x;
                o.y = acc[i][j][q2 * 2 + 1] + bias2[j].y;
                if (c0 < 512) *(float2*)(g_off  + (size_t)r * 512 + c0)         = o;
                else          *(float2*)(g_attn + (size_t)r * 256 + (c0 - 512)) = o;
            }
        }
    }
}

// ---------------- kernel 1: mask -> packed bits + bounding box ---------------
__global__ __launch_bounds__(256) void mask_kernel(const float* __restrict__ masks) {
    int b = blockIdx.x;
    const float4* m = (const float4*)(masks + (size_t)b * 16384);
    __shared__ unsigned colOrW[8][4];
    __shared__ unsigned char rowAny[128];
    __shared__ unsigned rowBits[4];
    int t = threadIdx.x, lane = t & 31, w = t >> 5;
    unsigned co[4] = {0, 0, 0, 0};
    unsigned* bo = g_bits + (size_t)b * 512;

    #pragma unroll
    for (int it = 0; it < 16; it++) {
        int row = it * 8 + w;
        float4 v = m[row * 32 + lane];
        unsigned b0 = __ballot_sync(0xffffffffu, v.x > 0.f);
        unsigned b1 = __ballot_sync(0xffffffffu, v.y > 0.f);
        unsigned b2 = __ballot_sync(0xffffffffu, v.z > 0.f);
        unsigned b3 = __ballot_sync(0xffffffffu, v.w > 0.f);
        co[0] |= b0; co[1] |= b1; co[2] |= b2; co[3] |= b3;
        if (lane == 0) rowAny[row] = ((b0 | b1 | b2 | b3) != 0u);
        if (lane < 4) {
            unsigned bb = (lane == 0) ? b0 : (lane == 1) ? b1 : (lane == 2) ? b2 : b3;
            bo[row * 4 + lane] = bb;
        }
    }
    if (lane < 4)
        colOrW[w][lane] = (lane == 0) ? co[0] : (lane == 1) ? co[1] : (lane == 2) ? co[2] : co[3];
    __syncthreads();

    if (t < 128) {
        unsigned rb = __ballot_sync(0xffffffffu, rowAny[t] != 0);
        if (lane == 0) rowBits[t >> 5] = rb;
    }
    __syncthreads();

    if (t == 0) {
        int xmin = 128, xmax = -1, ymin = 128, ymax = -1;
        #pragma unroll
        for (int j = 0; j < 4; j++) {
            unsigned v = 0;
            #pragma unroll
            for (int ww = 0; ww < 8; ww++) v |= colOrW[ww][j];
            if (v) {
                int lo = 4 * (__ffs(v) - 1) + j;  if (lo < xmin) xmin = lo;
                int hi = 4 * (31 - __clz(v)) + j; if (hi > xmax) xmax = hi;
            }
            unsigned r = rowBits[j];
            if (r) {
                int lo = __ffs(r) - 1 + 32 * j;  if (lo < ymin) ymin = lo;
                int hi = 31 - __clz(r) + 32 * j; if (hi > ymax) ymax = hi;
            }
        }
        float4 box;
        if (xmax >= 0) {
            float x0 = xmin * (1.f/128.f), x1 = (xmax + 1) * (1.f/128.f);
            float y0 = ymin * (1.f/128.f), y1 = (ymax + 1) * (1.f/128.f);
            box = make_float4((x0 + x1) * 0.5f, (y0 + y1) * 0.5f, x1 - x0, y1 - y0);
        } else {
            box = make_float4(0.f, 0.f, 0.f, 0.f);
        }
        ((float4*)g_box)[b] = box;
    }
}

// ---------------- fp32 tiled SGEMM (small out-projection only) --------------
template<int BM, int BN, int BK, int TM, int TN>
__global__ __launch_bounds__((BM/TM)*(BN/TN))
void sgemm_kernel(const float* __restrict__ A, const float* __restrict__ B,
                  const float* __restrict__ bias,
                  float* __restrict__ Cmat, int M, int N, int K) {
    constexpr int THREADS = (BM/TM)*(BN/TN);
    __shared__ float As[BK][BM];
    __shared__ float Bs[BK][BN];
    const int block_row = blockIdx.y * BM;
    const int block_col = blockIdx.x * BN;
    const int tid  = threadIdx.x;
    const int tcol = tid % (BN/TN);
    const int trow = tid / (BN/TN);

    float acc[TM][TN];
    #pragma unroll
    for (int i = 0; i < TM; i++)
        #pragma unroll
        for (int j = 0; j < TN; j++) acc[i][j] = 0.f;

    constexpr int AV = (BM*BK)/(4*THREADS);
    constexpr int BV = (BK*BN)/(4*THREADS);

    for (int k0 = 0; k0 < K; k0 += BK) {
        #pragma unroll
        for (int i = 0; i < AV; i++) {
            int v = tid + i * THREADS;
            int r  = v / (BK/4);
            int c4 = (v % (BK/4)) * 4;
            int rg = block_row + r; if (rg > M - 1) rg = M - 1;
            float4 a = *(const float4*)(A + (size_t)rg * K + k0 + c4);
            As[c4+0][r] = a.x; As[c4+1][r] = a.y; As[c4+2][r] = a.z; As[c4+3][r] = a.w;
        }
        #pragma unroll
        for (int i = 0; i < BV; i++) {
            int v = tid + i * THREADS;
            int r  = v / (BN/4);
            int c4 = (v % (BN/4)) * 4;
            *(float4*)(&Bs[r][c4]) = *(const float4*)(B + (size_t)(k0 + r) * N + block_col + c4);
        }
        __syncthreads();

        #pragma unroll
        for (int k = 0; k < BK; k++) {
            float ra[TM], rb[TN];
            #pragma unroll
            for (int i = 0; i < TM/2; i++) {
                ra[i]        = As[k][trow*(TM/2) + i];
                ra[i + TM/2] = As[k][BM/2 + trow*(TM/2) + i];
            }
            #pragma unroll
            for (int j = 0; j < TN/2; j++) {
                rb[j]        = Bs[k][tcol*(TN/2) + j];
                rb[j + TN/2] = Bs[k][BN/2 + tcol*(TN/2) + j];
            }
            #pragma unroll
            for (int i = 0; i < TM; i++)
                #pragma unroll
                for (int j = 0; j < TN; j++)
                    acc[i][j] += ra[i] * rb[j];
        }
        __syncthreads();
    }

    #pragma unroll
    for (int i = 0; i < TM; i++) {
        int rr = (i < TM/2) ? trow*(TM/2) + i : BM/2 + trow*(TM/2) + (i - TM/2);
        int r = block_row + rr;
        if (r >= M) continue;
        #pragma unroll
        for (int j = 0; j < TN; j++) {
            int cc = (j < TN/2) ? tcol*(TN/2) + j : BN/2 + tcol*(TN/2) + (j - TN/2);
            int c = block_col + cc;
            Cmat[(size_t)r * N + c] = acc[i][j] + bias[c];
        }
    }
}

// ---------------- kernel 4: sampling + softmax + bilinear gather -------------
// Phase A: lane = point. Phase B restructured: lane = (corner-pair cp, dim-pair
// d2); each thread gathers __half2 (2 channels) for corners {cp, cp+2},
// halving warp LDG issues (128 -> 64); shfl_xor(16) folds corner pairs.
__global__ __launch_bounds__(256) void sample_kernel() {
    int b = blockIdx.x;
    int n = b / LQ;
    int t = threadIdx.x, lane = t & 31, h = t >> 5;
    __shared__ int   s_idx[8][32][4];
    __shared__ float s_w[8][32][4];

    const int Wl_[4]    = {128, 64, 32, 16};
    const int start_[4] = {0, 16384, 20480, 21504};

    float4 box = ((const float4*)g_box)[b];

    int p = lane, l = p >> 3;
    float ox = g_off[(size_t)b * 512 + (h * 32 + p) * 2 + 0];
    float oy = g_off[(size_t)b * 512 + (h * 32 + p) * 2 + 1];
    float locx = box.x + ox * (1.f / 16.f) * box.z;
    float locy = box.y + oy * (1.f / 16.f) * box.w;

    int px = (int)(locx * 128.f); px = min(max(px, 0), 127);
    int py = (int)(locy * 128.f); py = min(max(py, 0), 127);
    // layout: word = y*4 + (x&3), bit = x>>2
    unsigned wbits = g_bits[(size_t)b * 512 + py * 4 + (px & 3)];
    float pin = ((wbits >> (px >> 2)) & 1u) ? 1.f : 0.f;

    float logit = g_attn[(size_t)b * 256 + h * 32 + p] * pin;
    float mx = logit;
    #pragma unroll
    for (int o = 16; o; o >>= 1) mx = fmaxf(mx, __shfl_xor_sync(0xffffffffu, mx, o));
    float e = expf(logit - mx);
    float sm = e;
    #pragma unroll
    for (int o = 16; o; o >>= 1) sm += __shfl_xor_sync(0xffffffffu, sm, o);
    float aw = e / sm;

    int Wl = Wl_[l], Hl = Wl;
    float pxf = locx * (float)Wl - 0.5f;
    float pyf = locy * (float)Hl - 0.5f;
    float x0f = floorf(pxf), y0f = floorf(pyf);
    float wx = pxf - x0f, wy = pyf - y0f;
    int x0 = (int)x0f, y0 = (int)y0f;
    int base = n * LEN_IN + start_[l];

    #pragma unroll
    for (int k = 0; k < 4; k++) {
        int xi = x0 + (k & 1), yi = y0 + (k >> 1);
        float cw = ((k & 1) ? wx : 1.f - wx) * ((k >> 1) ? wy : 1.f - wy);
        bool valid = (xi >= 0) && (xi < Wl) && (yi >= 0) && (yi < Hl);
        int xc = min(max(xi, 0), Wl - 1);
        int yc = min(max(yi, 0), Hl - 1);
        s_idx[h][p][k] = base + yc * Wl + xc;
        s_w[h][p][k]   = valid ? cw * aw : 0.f;
    }
    __syncwarp();

    // ---- phase B: half2 gathers over 2 corners per thread
    const int cp = lane >> 4;            // corner pair: {cp, cp+2}
    const int d2 = lane & 15;            // dim pair -> dims 2*d2, 2*d2+1
    const __half* vbase = g_valh + h * 32 + 2 * d2;
    float2 acc2 = make_float2(0.f, 0.f);
    #pragma unroll 4
    for (int pp = 0; pp < 32; pp++) {
        #pragma unroll
        for (int kk = 0; kk < 2; kk++) {
            const int k = cp + 2 * kk;
            float wgt = s_w[h][pp][k];
            if (wgt != 0.f) {
                __half2 v = *(const __half2*)(vbase + (size_t)s_idx[h][pp][k] * 256);
                float2 vf = __half22float2(v);
                acc2.x += wgt * vf.x;
                acc2.y += wgt * vf.y;
            }
        }
    }
    // fold the two corner pairs (lanes 0..15 <- lanes 16..31)
    acc2.x += __shfl_xor_sync(0xffffffffu, acc2.x, 16);
    acc2.y += __shfl_xor_sync(0xffffffffu, acc2.y, 16);
    if (cp == 0)
        *(float2*)(g_samp + (size_t)b * 256 + h * 32 + 2 * d2) = acc2;
}

// ---------------- launch --------------------------------------------------
extern "C" void kernel_launch(void* const* d_in, const int* in_sizes, int n_in,
                              void* d_out, int out_size) {
    const float* query = (const float*)d_in[0];
    const float* masks = (const float*)d_in[2];
    const float* flat  = (const float*)d_in[4];
    const unsigned char* pad = (const unsigned char*)d_in[7];
    const float* Woff  = (const float*)d_in[8];
    const float* boff  = (const float*)d_in[9];
    const float* Wattn = (const float*)d_in[10];
    const float* battn = (const float*)d_in[11];
    const float* Wval  = (const float*)d_in[12];
    const float* bval  = (const float*)d_in[13];
    const float* Wout  = (const float*)d_in[14];
    const float* bout  = (const float*)d_in[15];
    float* out = (float*)d_out;

    float* sampp = nullptr;
    cudaGetSymbolAddress((void**)&sampp, g_samp);

    cudaFuncSetAttribute(value_gemm, cudaFuncAttributeMaxDynamicSharedMemorySize, VG_SMEM);

    // --- fork two side streams off the capture stream (R8 pattern, guard-safe)
    cudaStream_t s1, s2;
    cudaStreamCreateWithFlags(&s1, cudaStreamNonBlocking);
    cudaStreamCreateWithFlags(&s2, cudaStreamNonBlocking);
    cudaEvent_t evRoot, ev1, ev2;
    cudaEventCreateWithFlags(&evRoot, cudaEventDisableTiming);
    cudaEventCreateWithFlags(&ev1, cudaEventDisableTiming);
    cudaEventCreateWithFlags(&ev2, cudaEventDisableTiming);

    cudaEventRecord(evRoot, 0);
    cudaStreamWaitEvent(s1, evRoot, 0);
    cudaStreamWaitEvent(s2, evRoot, 0);

    // main stream: value-projection path (tensor/L1-bound)
    prep_Bval<<<32, 256>>>(Wval);
    value_gemm<<<MROWS/64, 256, VG_SMEM>>>(flat, pad, bval);

    // s1: mask path (DRAM-bound) — overlaps value_gemm
    mask_kernel<<<NQ, 256, 0, s1>>>(masks);

    // s2: offsets/logits projection — overlaps value_gemm
    prep_Bproj<<<192, 256, 0, s2>>>(Woff, Wattn);
    proj_gemm<<<dim3((NQ + 127)/128, 6), 256, 0, s2>>>(query, boff, battn);

    // join
    cudaEventRecord(ev1, s1);
    cudaEventRecord(ev2, s2);
    cudaStreamWaitEvent(0, ev1, 0);
    cudaStreamWaitEvent(0, ev2, 0);

    // softmax + bilinear sampling, then out-projection
    sample_kernel<<<NQ, 256>>>();
    sgemm_kernel<64,64,16,4,4><<<dim3(CDIM/64, (NQ + 63)/64), 256>>>(
        sampp, Wout, bout, out, NQ, CDIM, CDIM);

    // destroy only when NOT capturing (destroying capture-attached objects
    // would invalidate the graph); leaked once on the capture call is fine.
    cudaStreamCaptureStatus st = cudaStreamCaptureStatusNone;
    cudaStreamIsCapturing(0, &st);
    if (st == cudaStreamCaptureStatusNone) {
        cudaEventDestroy(evRoot);
        cudaEventDestroy(ev1);
        cudaEventDestroy(ev2);
        cudaStreamDestroy(s1);
        cudaStreamDestroy(s2);
    }
}

// round 12
// speedup vs baseline: 1.0498x; 1.0034x over previous
#include <cuda_runtime.h>
#include <cuda_fp16.h>
#include <math.h>
#include <stdint.h>

// Problem constants (fixed by the dataset)
#define NB      8
#define LQ      300
#define CDIM    256
#define HEADS   8
#define NLVL    4
#define NPTS    8
#define DHEAD   32
#define LEN_IN  21760
#define NQ      (NB*LQ)         // 2400
#define MROWS   (NB*LEN_IN)     // 174080

// ---------------- scratch (device globals; no allocations allowed) ----------
__device__ __half   g_valh[(size_t)MROWS * CDIM];    // projected value (fp16), 89 MB
__device__ unsigned g_bits[NQ * 512];                // packed mask: word=(y*4+(x&3)), bit=x>>2
__device__ float    g_box[NQ * 4];                   // cx, cy, w, h
__device__ float    g_off[NQ * 512];                 // sampling offsets (h,l,p,2)
__device__ float    g_attn[NQ * 256];                // raw attention logits (h,l,p)
__device__ float    g_samp[NQ * 256];                // sampled output before W_out
// W_val^T fragments: ((ntile*8 + kpair)*32 + lane) -> uint4 {ks even b0,b1, ks odd b0,b1}
__device__ uint4    g_Bf4[32 * 8 * 32];
// [Woff | Wattn] (N=768) in B-fragment layout, fp16 hi/lo splits (3-term, exact).
__device__ uint2    g_PfHi[96 * 16 * 32];
__device__ uint2    g_PfLo[96 * 16 * 32];

// ---------------- helpers ----------------------------------------------------
__device__ __forceinline__ void mma16816(float* c, const uint32_t* a, const uint2 b) {
    asm volatile(
        "mma.sync.aligned.m16n8k16.row.col.f32.f16.f16.f32 "
        "{%0,%1,%2,%3}, {%4,%5,%6,%7}, {%8,%9}, {%0,%1,%2,%3};\n"
        : "+f"(c[0]), "+f"(c[1]), "+f"(c[2]), "+f"(c[3])
        : "r"(a[0]), "r"(a[1]), "r"(a[2]), "r"(a[3]), "r"(b.x), "r"(b.y));
}
__device__ __forceinline__ uint32_t cvt_h(float2 v) {
    __half2 h = __float22half2_rn(v);
    return *(uint32_t*)&h;
}
__device__ __forceinline__ void cvt_hilo(float2 v, uint32_t& hi, uint32_t& lo) {
    __half2 h = __float22half2_rn(v);
    float2 f = __half22float2(h);
    __half2 l = __float22half2_rn(make_float2(v.x - f.x, v.y - f.y));
    hi = *(uint32_t*)&h;
    lo = *(uint32_t*)&l;
}
__device__ __forceinline__ uint32_t smem_u32(const void* p) {
    uint32_t a;
    asm("{ .reg .u64 t; cvta.to.shared.u64 t, %1; cvt.u32.u64 %0, t; }" : "=r"(a) : "l"(p));
    return a;
}
__device__ __forceinline__ void cp_async16(uint32_t dst, const void* src) {
    asm volatile("cp.async.cg.shared.global [%0], [%1], 16;" :: "r"(dst), "l"(src));
}
__device__ __forceinline__ void cp_commit() { asm volatile("cp.async.commit_group;" ::: "memory"); }
template<int N> __device__ __forceinline__ void cp_wait() {
    asm volatile("cp.async.wait_group %0;" :: "n"(N) : "memory");
}
__device__ __forceinline__ void ldm_x4(uint32_t* r, uint32_t addr) {
    asm volatile("ldmatrix.sync.aligned.m8n8.x4.shared.b16 {%0,%1,%2,%3}, [%4];"
        : "=r"(r[0]), "=r"(r[1]), "=r"(r[2]), "=r"(r[3]) : "r"(addr));
}

// ================= prep: W_val^T -> fp16 uint4 fragment pairs ===============
__global__ __launch_bounds__(256) void prep_Bval(const float* __restrict__ W) {
    int idx = blockIdx.x * 256 + threadIdx.x;     // 8192 threads
    int lane  = idx & 31;
    int gkp   = (idx >> 5) & 7;                   // k-pair 0..7
    int ntile = idx >> 8;                         // 0..31
    int n  = ntile * 8 + (lane >> 2);
    uint32_t r[4];
    #pragma unroll
    for (int h2 = 0; h2 < 2; h2++) {
        int kb = (gkp * 2 + h2) * 16 + (lane & 3) * 2;
        r[h2*2+0] = cvt_h(make_float2(W[(kb + 0) * 256 + n], W[(kb + 1) * 256 + n]));
        r[h2*2+1] = cvt_h(make_float2(W[(kb + 8) * 256 + n], W[(kb + 9) * 256 + n]));
    }
    g_Bf4[idx] = make_uint4(r[0], r[1], r[2], r[3]);
}

// ================= prep: [Woff | Wattn]^T -> fp16 hi/lo fragments ===========
__global__ __launch_bounds__(256) void prep_Bproj(
        const float* __restrict__ Woff, const float* __restrict__ Wattn) {
    int idx = blockIdx.x * 256 + threadIdx.x;     // 49152 threads
    int lane  = idx & 31;
    int ks    = (idx >> 5) & 15;
    int ntile = idx >> 9;                         // 0..95
    int n  = ntile * 8 + (lane >> 2);             // 0..767
    int kb = ks * 16 + (lane & 3) * 2;
    float x[4];
    #pragma unroll
    for (int q = 0; q < 4; q++) {
        int k = kb + (q >> 1) * 8 + (q & 1);
        x[q] = (n < 512) ? Woff[k * 512 + n] : Wattn[k * 256 + (n - 512)];
    }
    uint32_t h0, l0, h1, l1;
    cvt_hilo(make_float2(x[0], x[1]), h0, l0);
    cvt_hilo(make_float2(x[2], x[3]), h1, l1);
    g_PfHi[idx] = make_uint2(h0, h1);
    g_PfLo[idx] = make_uint2(l0, l1);
}

// ================= kernel: fp16 HMMA value GEMM (64x256 CTA tile) ===========
// 8 warps: 2(M)x4(N), warp tile 32x64. fp32 A staged via 2-deep cp.async and
// converted to an fp16 ldmatrix tile; B fragments staged via 2-deep cp.async
// into smem (LDS.128 consumption — kills the L2-latency stall chain).
#define SROWF   68                       // floats per fp32 stage row (64 + 4 pad)
#define STAGEF  (64 * SROWF)             // floats per A stage (17408 B)
#define HROW    72                       // halves per fp16 row (144 B, conflict-free)
#define A_BYTES (2 * STAGEF * 4)         // 34816
#define H_OFF   A_BYTES
#define H_BYTES (64 * HROW * 2)          // 9216
#define B_OFF   (H_OFF + H_BYTES)        // 44032 (16B aligned)
#define B_STAGE 32768                    // 32 ntiles x 2 kp x 32 lanes x 16 B
#define VG_SMEM (B_OFF + 2 * B_STAGE)    // 109568 bytes -> 2 CTAs/SM

__global__ __launch_bounds__(256, 2) void value_gemm(
        const float* __restrict__ A, const unsigned char* __restrict__ pad,
        const float* __restrict__ bias) {
    extern __shared__ float smf[];
    __half* smh = (__half*)((char*)smf + H_OFF);
    const uint32_t sb  = smem_u32(smf);
    const uint32_t sbh = smem_u32(smh);
    const int tid = threadIdx.x, lane = tid & 31, wid = tid >> 5;
    const int g = lane >> 2, t = lane & 3;
    const int wm = (wid >> 2) * 32;          // warp M offset (0/32)
    const int wn = (wid & 3) * 64;           // warp N offset
    const int rowTile = blockIdx.x * 64;
    const int ntb = wn >> 3;

    float acc[2][8][4];
    #pragma unroll
    for (int i = 0; i < 2; i++)
        #pragma unroll
        for (int j = 0; j < 8; j++)
            #pragma unroll
            for (int q = 0; q < 4; q++) acc[i][j][q] = 0.f;

    // A chunk (64 k-cols) into A stage s
    #define ISSUE_A(c, s) { \
        _Pragma("unroll") \
        for (int u4 = 0; u4 < 4; u4++) { \
            int u = tid + u4 * 256; \
            int row = u >> 4, seg = u & 15; \
            cp_async16(sb + ((s) * STAGEF + row * SROWF + seg * 4) * 4, \
                       A + (size_t)(rowTile + row) * 256 + (c) * 64 + seg * 4); \
        } }
    // B chunk slice (32 ntiles x 2 kpairs) into B stage s
    #define ISSUE_B(c, s) { \
        _Pragma("unroll") \
        for (int i = 0; i < 8; i++) { \
            int d = tid + i * 256; \
            int lane_d = d & 31, kp_d = (d >> 5) & 1, nt_d = d >> 6; \
            cp_async16(sb + B_OFF + (s) * B_STAGE + d * 16, \
                       g_Bf4 + ((nt_d * 8 + (c) * 2 + kp_d) * 32 + lane_d)); \
        } }

    ISSUE_A(0, 0); ISSUE_B(0, 0); cp_commit();
    ISSUE_A(1, 1); ISSUE_B(1, 1); cp_commit();

    const int crow = tid >> 2, ccg = tid & 3;        // convert-phase mapping

    #pragma unroll
    for (int c = 0; c < 4; c++) {
        const int st = c & 1;
        if (c < 3) cp_wait<1>(); else cp_wait<0>();
        __syncthreads();                              // chunk c arrived; hbuf readers done

        // ---- cooperative fp32 -> fp16 conversion into ldmatrix-layout tile
        {
            const float* src = smf + st * STAGEF + crow * SROWF + ccg * 16;
            uint32_t h[8];
            #pragma unroll
            for (int i = 0; i < 8; i++)
                h[i] = cvt_h(make_float2(src[2*i], src[2*i+1]));
            uint4* dst = (uint4*)(smh + crow * HROW + ccg * 16);
            dst[0] = make_uint4(h[0], h[1], h[2], h[3]);
            dst[1] = make_uint4(h[4], h[5], h[6], h[7]);
        }
        __syncthreads();                              // hbuf published

        // ---- MMA phase: A via ldmatrix, B via conflict-free LDS.128
        const uint4* Bs = (const uint4*)((char*)smf + B_OFF + st * B_STAGE);
        #pragma unroll
        for (int kp = 0; kp < 2; kp++) {
            uint4 b4[8];
            #pragma unroll
            for (int j = 0; j < 8; j++)
                b4[j] = Bs[((ntb + j) * 2 + kp) * 32 + lane];
            #pragma unroll
            for (int h2 = 0; h2 < 2; h2++) {
                const int ksl = kp * 2 + h2;
                uint32_t a[2][4];
                #pragma unroll
                for (int i = 0; i < 2; i++) {
                    int lrow = wm + i * 16 + (lane & 15);
                    ldm_x4(a[i], sbh + lrow * (HROW * 2) + ksl * 32 + ((lane >> 4) << 4));
                }
                #pragma unroll
                for (int i = 0; i < 2; i++)
                    #pragma unroll
                    for (int j = 0; j < 8; j++)
                        mma16816(acc[i][j], a[i],
                                 h2 ? make_uint2(b4[j].z, b4[j].w)
                                    : make_uint2(b4[j].x, b4[j].y));
            }
        }
        if (c < 2) {
            __syncthreads();                          // all warps done with stage st
            ISSUE_A(c + 2, st); ISSUE_B(c + 2, st); cp_commit();
        }
    }
    #undef ISSUE_A
    #undef ISSUE_B

    // ---- epilogue: bias add, padding zero, fp16 stores
    #pragma unroll
    for (int i = 0; i < 2; i++) {
        int ra = rowTile + wm + i * 16 + g;
        int rb = ra + 8;
        bool pa = pad[ra] != 0, pb = pad[rb] != 0;
        #pragma unroll
        for (int j = 0; j < 8; j++) {
            int c0 = wn + j * 8 + t * 2;
            float2 bi = *(const float2*)(bias + c0);
            float2 oa, ob;
            oa.x = pa ? 0.f : acc[i][j][0] + bi.x;
            oa.y = pa ? 0.f : acc[i][j][1] + bi.y;
            ob.x = pb ? 0.f : acc[i][j][2] + bi.x;
            ob.y = pb ? 0.f : acc[i][j][3] + bi.y;
            *(__half2*)(g_valh + (size_t)ra * 256 + c0) = __float22half2_rn(oa);
            *(__half2*)(g_valh + (size_t)rb * 256 + c0) = __float22half2_rn(ob);
        }
    }
}

// ================= kernel: HMMA 3-term fp16 proj GEMM =======================
__global__ __launch_bounds__(256) void proj_gemm(
        const float* __restrict__ Q,
        const float* __restrict__ boff, const float* __restrict__ battn) {
    const int tid = threadIdx.x, lane = tid & 31, wid = tid >> 5;
    const int g = lane >> 2, t = lane & 3;
    const int rowBase = blockIdx.x * 128 + (wid & 3) * 32 + g;
    const int colBase = blockIdx.y * 128 + (wid >> 2) * 64;
    const int ntb = colBase >> 3;

    float2 bias2[8];
    #pragma unroll
    for (int j = 0; j < 8; j++) {
        int c = colBase + j * 8 + t * 2;
        bias2[j] = (c < 512) ? *(const float2*)(boff + c)
                             : *(const float2*)(battn + (c - 512));
    }

    float acc[2][8][4];
    #pragma unroll
    for (int i = 0; i < 2; i++)
        #pragma unroll
        for (int j = 0; j < 8; j++)
            #pragma unroll
            for (int q = 0; q < 4; q++) acc[i][j][q] = 0.f;

    float2 araw[2][2][4];
    #define LOAD_AQ(ks, buf) { \
        _Pragma("unroll") \
        for (int i = 0; i < 2; i++) { \
            int r0 = min(rowBase + i * 16, NQ - 1); \
            int r1 = min(rowBase + i * 16 + 8, NQ - 1); \
            const float* b0 = Q + (size_t)r0 * 256 + (ks) * 16 + t * 2; \
            const float* b1 = Q + (size_t)r1 * 256 + (ks) * 16 + t * 2; \
            araw[buf][i][0] = *(const float2*)(b0); \
            araw[buf][i][1] = *(const float2*)(b1); \
            araw[buf][i][2] = *(const float2*)(b0 + 8); \
            araw[buf][i][3] = *(const float2*)(b1 + 8); \
        } }

    LOAD_AQ(0, 0);
    #pragma unroll
    for (int ks = 0; ks < 16; ks++) {
        const int cur = ks & 1;
        if (ks < 15) LOAD_AQ(ks + 1, cur ^ 1);

        uint2 bhi[8], blo[8];
        #pragma unroll
        for (int j = 0; j < 8; j++) {
            int bidx = ((ntb + j) * 16 + ks) * 32 + lane;
            bhi[j] = g_PfHi[bidx];
            blo[j] = g_PfLo[bidx];
        }
        uint32_t ahi[2][4], alo[2][4];
        #pragma unroll
        for (int i = 0; i < 2; i++)
            #pragma unroll
            for (int q = 0; q < 4; q++)
                cvt_hilo(araw[cur][i][q], ahi[i][q], alo[i][q]);

        #pragma unroll
        for (int i = 0; i < 2; i++)
            #pragma unroll
            for (int j = 0; j < 8; j++) {
                mma16816(acc[i][j], ahi[i], bhi[j]);
                mma16816(acc[i][j], ahi[i], blo[j]);
                mma16816(acc[i][j], alo[i], bhi[j]);
            }
    }
    #undef LOAD_AQ

    #pragma unroll
    for (int i = 0; i < 2; i++) {
        #pragma unroll
        for (int q2 = 0; q2 < 2; q2++) {
            int r = rowBase + i * 16 + q2 * 8;
            if (r >= NQ) continue;
            #pragma unroll
            for (int j = 0; j < 8; j++) {
                int c0 = colBase + j * 8 + t * 2;
                float2 o;
                o.x = acc[i][j][q2 * 2 + 0] + bias2[j].x;
                o.y = acc[i][j][q2 * 2 + 1] + bias2[j].y;
                if (c0 < 512) *(float2*)(g_off  + (size_t)r * 512 + c0)         = o;
                else          *(float2*)(g_attn + (size_t)r * 256 + (c0 - 512)) = o;
            }
        }
    }
}

// ---------------- kernel 1: mask -> packed bits + bounding box ---------------
__global__ __launch_bounds__(256) void mask_kernel(const float* __restrict__ masks) {
    int b = blockIdx.x;
    const float4* m = (const float4*)(masks + (size_t)b * 16384);
    __shared__ unsigned colOrW[8][4];
    __shared__ unsigned char rowAny[128];
    __shared__ unsigned rowBits[4];
    int t = threadIdx.x, lane = t & 31, w = t >> 5;
    unsigned co[4] = {0, 0, 0, 0};
    unsigned* bo = g_bits + (size_t)b * 512;

    #pragma unroll
    for (int it = 0; it < 16; it++) {
        int row = it * 8 + w;
        float4 v = m[row * 32 + lane];
        unsigned b0 = __ballot_sync(0xffffffffu, v.x > 0.f);
        unsigned b1 = __ballot_sync(0xffffffffu, v.y > 0.f);
        unsigned b2 = __ballot_sync(0xffffffffu, v.z > 0.f);
        unsigned b3 = __ballot_sync(0xffffffffu, v.w > 0.f);
        co[0] |= b0; co[1] |= b1; co[2] |= b2; co[3] |= b3;
        if (lane == 0) rowAny[row] = ((b0 | b1 | b2 | b3) != 0u);
        if (lane < 4) {
            unsigned bb = (lane == 0) ? b0 : (lane == 1) ? b1 : (lane == 2) ? b2 : b3;
            bo[row * 4 + lane] = bb;
        }
    }
    if (lane < 4)
        colOrW[w][lane] = (lane == 0) ? co[0] : (lane == 1) ? co[1] : (lane == 2) ? co[2] : co[3];
    __syncthreads();

    if (t < 128) {
        unsigned rb = __ballot_sync(0xffffffffu, rowAny[t] != 0);
        if (lane == 0) rowBits[t >> 5] = rb;
    }
    __syncthreads();

    if (t == 0) {
        int xmin = 128, xmax = -1, ymin = 128, ymax = -1;
        #pragma unroll
        for (int j = 0; j < 4; j++) {
            unsigned v = 0;
            #pragma unroll
            for (int ww = 0; ww < 8; ww++) v |= colOrW[ww][j];
            if (v) {
                int lo = 4 * (__ffs(v) - 1) + j;  if (lo < xmin) xmin = lo;
                int hi = 4 * (31 - __clz(v)) + j; if (hi > xmax) xmax = hi;
            }
            unsigned r = rowBits[j];
            if (r) {
                int lo = __ffs(r) - 1 + 32 * j;  if (lo < ymin) ymin = lo;
                int hi = 31 - __clz(r) + 32 * j; if (hi > ymax) ymax = hi;
            }
        }
        float4 box;
        if (xmax >= 0) {
            float x0 = xmin * (1.f/128.f), x1 = (xmax + 1) * (1.f/128.f);
            float y0 = ymin * (1.f/128.f), y1 = (ymax + 1) * (1.f/128.f);
            box = make_float4((x0 + x1) * 0.5f, (y0 + y1) * 0.5f, x1 - x0, y1 - y0);
        } else {
            box = make_float4(0.f, 0.f, 0.f, 0.f);
        }
        ((float4*)g_box)[b] = box;
    }
}

// ---------------- fp32 tiled SGEMM (small out-projection only) --------------
template<int BM, int BN, int BK, int TM, int TN>
__global__ __launch_bounds__((BM/TM)*(BN/TN))
void sgemm_kernel(const float* __restrict__ A, const float* __restrict__ B,
                  const float* __restrict__ bias,
                  float* __restrict__ Cmat, int M, int N, int K) {
    constexpr int THREADS = (BM/TM)*(BN/TN);
    __shared__ float As[BK][BM];
    __shared__ float Bs[BK][BN];
    const int block_row = blockIdx.y * BM;
    const int block_col = blockIdx.x * BN;
    const int tid  = threadIdx.x;
    const int tcol = tid % (BN/TN);
    const int trow = tid / (BN/TN);

    float acc[TM][TN];
    #pragma unroll
    for (int i = 0; i < TM; i++)
        #pragma unroll
        for (int j = 0; j < TN; j++) acc[i][j] = 0.f;

    constexpr int AV = (BM*BK)/(4*THREADS);
    constexpr int BV = (BK*BN)/(4*THREADS);

    for (int k0 = 0; k0 < K; k0 += BK) {
        #pragma unroll
        for (int i = 0; i < AV; i++) {
            int v = tid + i * THREADS;
            int r  = v / (BK/4);
            int c4 = (v % (BK/4)) * 4;
            int rg = block_row + r; if (rg > M - 1) rg = M - 1;
            float4 a = *(const float4*)(A + (size_t)rg * K + k0 + c4);
            As[c4+0][r] = a.x; As[c4+1][r] = a.y; As[c4+2][r] = a.z; As[c4+3][r] = a.w;
        }
        #pragma unroll
        for (int i = 0; i < BV; i++) {
            int v = tid + i * THREADS;
            int r  = v / (BN/4);
            int c4 = (v % (BN/4)) * 4;
            *(float4*)(&Bs[r][c4]) = *(const float4*)(B + (size_t)(k0 + r) * N + block_col + c4);
        }
        __syncthreads();

        #pragma unroll
        for (int k = 0; k < BK; k++) {
            float ra[TM], rb[TN];
            #pragma unroll
            for (int i = 0; i < TM/2; i++) {
                ra[i]        = As[k][trow*(TM/2) + i];
                ra[i + TM/2] = As[k][BM/2 + trow*(TM/2) + i];
            }
            #pragma unroll
            for (int j = 0; j < TN/2; j++) {
                rb[j]        = Bs[k][tcol*(TN/2) + j];
                rb[j + TN/2] = Bs[k][BN/2 + tcol*(TN/2) + j];
            }
            #pragma unroll
            for (int i = 0; i < TM; i++)
                #pragma unroll
                for (int j = 0; j < TN; j++)
                    acc[i][j] += ra[i] * rb[j];
        }
        __syncthreads();
    }

    #pragma unroll
    for (int i = 0; i < TM; i++) {
        int rr = (i < TM/2) ? trow*(TM/2) + i : BM/2 + trow*(TM/2) + (i - TM/2);
        int r = block_row + rr;
        if (r >= M) continue;
        #pragma unroll
        for (int j = 0; j < TN; j++) {
            int cc = (j < TN/2) ? tcol*(TN/2) + j : BN/2 + tcol*(TN/2) + (j - TN/2);
            int c = block_col + cc;
            Cmat[(size_t)r * N + c] = acc[i][j] + bias[c];
        }
    }
}

// ---------------- kernel 4: sampling + softmax + bilinear gather -------------
// Phase A: lane = point. Phase B: lane = (corner-pair cp, dim-pair d2); each
// thread gathers __half2 for corners {cp, cp+2}; shfl_xor(16) folds pairs.
__global__ __launch_bounds__(256) void sample_kernel() {
    int b = blockIdx.x;
    int n = b / LQ;
    int t = threadIdx.x, lane = t & 31, h = t >> 5;
    __shared__ int   s_idx[8][32][4];
    __shared__ float s_w[8][32][4];

    const int Wl_[4]    = {128, 64, 32, 16};
    const int start_[4] = {0, 16384, 20480, 21504};

    float4 box = ((const float4*)g_box)[b];

    int p = lane, l = p >> 3;
    float ox = g_off[(size_t)b * 512 + (h * 32 + p) * 2 + 0];
    float oy = g_off[(size_t)b * 512 + (h * 32 + p) * 2 + 1];
    float locx = box.x + ox * (1.f / 16.f) * box.z;
    float locy = box.y + oy * (1.f / 16.f) * box.w;

    int px = (int)(locx * 128.f); px = min(max(px, 0), 127);
    int py = (int)(locy * 128.f); py = min(max(py, 0), 127);
    unsigned wbits = g_bits[(size_t)b * 512 + py * 4 + (px & 3)];
    float pin = ((wbits >> (px >> 2)) & 1u) ? 1.f : 0.f;

    float logit = g_attn[(size_t)b * 256 + h * 32 + p] * pin;
    float mx = logit;
    #pragma unroll
    for (int o = 16; o; o >>= 1) mx = fmaxf(mx, __shfl_xor_sync(0xffffffffu, mx, o));
    float e = expf(logit - mx);
    float sm = e;
    #pragma unroll
    for (int o = 16; o; o >>= 1) sm += __shfl_xor_sync(0xffffffffu, sm, o);
    float aw = e / sm;

    int Wl = Wl_[l], Hl = Wl;
    float pxf = locx * (float)Wl - 0.5f;
    float pyf = locy * (float)Hl - 0.5f;
    float x0f = floorf(pxf), y0f = floorf(pyf);
    float wx = pxf - x0f, wy = pyf - y0f;
    int x0 = (int)x0f, y0 = (int)y0f;
    int base = n * LEN_IN + start_[l];

    #pragma unroll
    for (int k = 0; k < 4; k++) {
        int xi = x0 + (k & 1), yi = y0 + (k >> 1);
        float cw = ((k & 1) ? wx : 1.f - wx) * ((k >> 1) ? wy : 1.f - wy);
        bool valid = (xi >= 0) && (xi < Wl) && (yi >= 0) && (yi < Hl);
        int xc = min(max(xi, 0), Wl - 1);
        int yc = min(max(yi, 0), Hl - 1);
        s_idx[h][p][k] = base + yc * Wl + xc;
        s_w[h][p][k]   = valid ? cw * aw : 0.f;
    }
    __syncwarp();

    const int cp = lane >> 4;            // corner pair: {cp, cp+2}
    const int d2 = lane & 15;            // dim pair -> dims 2*d2, 2*d2+1
    const __half* vbase = g_valh + h * 32 + 2 * d2;
    float2 acc2 = make_float2(0.f, 0.f);
    #pragma unroll 4
    for (int pp = 0; pp < 32; pp++) {
        #pragma unroll
        for (int kk = 0; kk < 2; kk++) {
            const int k = cp + 2 * kk;
            float wgt = s_w[h][pp][k];
            if (wgt != 0.f) {
                __half2 v = *(const __half2*)(vbase + (size_t)s_idx[h][pp][k] * 256);
                float2 vf = __half22float2(v);
                acc2.x += wgt * vf.x;
                acc2.y += wgt * vf.y;
            }
        }
    }
    acc2.x += __shfl_xor_sync(0xffffffffu, acc2.x, 16);
    acc2.y += __shfl_xor_sync(0xffffffffu, acc2.y, 16);
    if (cp == 0)
        *(float2*)(g_samp + (size_t)b * 256 + h * 32 + 2 * d2) = acc2;
}

// ---------------- launch --------------------------------------------------
extern "C" void kernel_launch(void* const* d_in, const int* in_sizes, int n_in,
                              void* d_out, int out_size) {
    const float* query = (const float*)d_in[0];
    const float* masks = (const float*)d_in[2];
    const float* flat  = (const float*)d_in[4];
    const unsigned char* pad = (const unsigned char*)d_in[7];
    const float* Woff  = (const float*)d_in[8];
    const float* boff  = (const float*)d_in[9];
    const float* Wattn = (const float*)d_in[10];
    const float* battn = (const float*)d_in[11];
    const float* Wval  = (const float*)d_in[12];
    const float* bval  = (const float*)d_in[13];
    const float* Wout  = (const float*)d_in[14];
    const float* bout  = (const float*)d_in[15];
    float* out = (float*)d_out;

    float* sampp = nullptr;
    cudaGetSymbolAddress((void**)&sampp, g_samp);

    cudaFuncSetAttribute(value_gemm, cudaFuncAttributeMaxDynamicSharedMemorySize, VG_SMEM);

    // --- fork two side streams off the capture stream (R8 pattern, guard-safe)
    cudaStream_t s1, s2;
    cudaStreamCreateWithFlags(&s1, cudaStreamNonBlocking);
    cudaStreamCreateWithFlags(&s2, cudaStreamNonBlocking);
    cudaEvent_t evRoot, ev1, ev2;
    cudaEventCreateWithFlags(&evRoot, cudaEventDisableTiming);
    cudaEventCreateWithFlags(&ev1, cudaEventDisableTiming);
    cudaEventCreateWithFlags(&ev2, cudaEventDisableTiming);

    cudaEventRecord(evRoot, 0);
    cudaStreamWaitEvent(s1, evRoot, 0);
    cudaStreamWaitEvent(s2, evRoot, 0);

    // main stream: value-projection path (tensor-bound)
    prep_Bval<<<32, 256>>>(Wval);
    value_gemm<<<MROWS/64, 256, VG_SMEM>>>(flat, pad, bval);

    // s1: mask path (DRAM-bound) — overlaps value_gemm
    mask_kernel<<<NQ, 256, 0, s1>>>(masks);

    // s2: offsets/logits projection — overlaps value_gemm
    prep_Bproj<<<192, 256, 0, s2>>>(Woff, Wattn);
    proj_gemm<<<dim3((NQ + 127)/128, 6), 256, 0, s2>>>(query, boff, battn);

    // join
    cudaEventRecord(ev1, s1);
    cudaEventRecord(ev2, s2);
    cudaStreamWaitEvent(0, ev1, 0);
    cudaStreamWaitEvent(0, ev2, 0);

    // softmax + bilinear sampling, then out-projection
    sample_kernel<<<NQ, 256>>>();
    sgemm_kernel<64,64,16,4,4><<<dim3(CDIM/64, (NQ + 63)/64), 256>>>(
        sampp, Wout, bout, out, NQ, CDIM, CDIM);

    // destroy only when NOT capturing (destroying capture-attached objects
    // would invalidate the graph); leaked once on the capture call is fine.
    cudaStreamCaptureStatus st = cudaStreamCaptureStatusNone;
    cudaStreamIsCapturing(0, &st);
    if (st == cudaStreamCaptureStatusNone) {
        cudaEventDestroy(evRoot);
        cudaEventDestroy(ev1);
        cudaEventDestroy(ev2);
        cudaStreamDestroy(s1);
        cudaStreamDestroy(s2);
    }
}